// round 14
// baseline (speedup 1.0000x reference)
#include <cuda_runtime.h>
#include <cuda_fp16.h>
#include <cstdint>

#define N_NODES 100000
#define N_EDGES 1600000
#define CC 64
#define NL 3
#define SCAN_BLK 1024
#define N_SCANB ((N_NODES + SCAN_BLK - 1) / SCAN_BLK)   // 98

// Static device scratch (allowed).
__device__ __half g_h  [N_NODES * CC];          // agg output (fp16 ~ tf32 mantissa)
__device__ __half g_xh0[N_NODES * CC];          // fp16 copy of input x
__device__ __half g_xha[N_NODES * CC];          // layer-0 output (fp16)
__device__ __half g_xhb[N_NODES * CC];          // layer-1 output (fp16)
__device__ int    g_cnt[N_NODES];
__device__ int    g_off[N_NODES];
__device__ int    g_cur[N_NODES];
__device__ int    g_csr[N_EDGES];
__device__ int    g_bsum[N_SCANB + 1];

// ---------------- tf32 mma helpers (sm_80+ baseline — no 'a' features) -----

__device__ __forceinline__ uint32_t f2tf32(float f) {
    uint32_t r;
    asm("cvt.rna.tf32.f32 %0, %1;" : "=r"(r) : "f"(f));
    return r;
}

__device__ __forceinline__ void mma_tf32(float* d,
                                         uint32_t a0, uint32_t a1,
                                         uint32_t a2, uint32_t a3,
                                         uint32_t b0, uint32_t b1) {
    asm volatile(
        "mma.sync.aligned.m16n8k8.row.col.f32.tf32.tf32.f32 "
        "{%0,%1,%2,%3}, {%4,%5,%6,%7}, {%8,%9}, {%0,%1,%2,%3};"
        : "+f"(d[0]), "+f"(d[1]), "+f"(d[2]), "+f"(d[3])
        : "r"(a0), "r"(a1), "r"(a2), "r"(a3), "r"(b0), "r"(b1));
}

// ---------------- CSR build (once per launch) -------------------------------

__global__ void hist_kernel(const int* __restrict__ ei, int* __restrict__ cnt) {
    int e = blockIdx.x * blockDim.x + threadIdx.x;
    if (e < N_EDGES) atomicAdd(&cnt[ei[N_EDGES + e]], 1);
}

__global__ void scan_blocks_kernel(const int* __restrict__ cnt,
                                   int* __restrict__ off, int* __restrict__ bsum) {
    __shared__ int sm[SCAN_BLK];
    int gid = blockIdx.x * SCAN_BLK + threadIdx.x;
    int v = (gid < N_NODES) ? cnt[gid] : 0;
    sm[threadIdx.x] = v;
    __syncthreads();
    #pragma unroll
    for (int o = 1; o < SCAN_BLK; o <<= 1) {
        int t = (threadIdx.x >= o) ? sm[threadIdx.x - o] : 0;
        __syncthreads();
        sm[threadIdx.x] += t;
        __syncthreads();
    }
    if (gid < N_NODES) off[gid] = sm[threadIdx.x] - v;
    if (threadIdx.x == SCAN_BLK - 1) bsum[blockIdx.x] = sm[threadIdx.x];
}

__global__ void scan_bsum_kernel(int* __restrict__ bsum) {
    __shared__ int sm[128];
    int t = threadIdx.x;
    int v = (t < N_SCANB) ? bsum[t] : 0;
    sm[t] = v;
    __syncthreads();
    #pragma unroll
    for (int o = 1; o < 128; o <<= 1) {
        int u = (t >= o) ? sm[t - o] : 0;
        __syncthreads();
        sm[t] += u;
        __syncthreads();
    }
    if (t < N_SCANB) bsum[t] = sm[t] - v;
}

__global__ void add_off_kernel(int* __restrict__ off, const int* __restrict__ bsum,
                               int* __restrict__ cur) {
    int gid = blockIdx.x * blockDim.x + threadIdx.x;
    if (gid < N_NODES) {
        int v = off[gid] + bsum[gid / SCAN_BLK];
        off[gid] = v;
        cur[gid] = v;
    }
}

__global__ void fill_csr_kernel(const int* __restrict__ ei,
                                int* __restrict__ cur, int* __restrict__ csr) {
    int e = blockIdx.x * blockDim.x + threadIdx.x;
    if (e < N_EDGES) {
        int d = ei[N_EDGES + e];
        int p = atomicAdd(&cur[d], 1);
        csr[p] = ei[e];
    }
}

// ---------------- x fp32 -> fp16 (once per launch) --------------------------

__global__ void x2h_kernel(const float* __restrict__ x, __half* __restrict__ xh) {
    int i = blockIdx.x * blockDim.x + threadIdx.x;
    if (i >= N_NODES * CC / 4) return;
    float4 v = ((const float4*)x)[i];
    __half2* p = (__half2*)xh + i * 2;
    p[0] = __floats2half2_rn(v.x, v.y);
    p[1] = __floats2half2_rn(v.z, v.w);
}

// ---------------- Aggregation: warp-per-node, fp16 gather, fp32 accum -------
// NOTE: this round launches agg TWICE per layer (idempotent) purely to
// measure T_agg from the dur delta vs the 239.7us baseline.

__global__ void __launch_bounds__(256)
agg_kernel(const __half* __restrict__ x, const int* __restrict__ off,
           const int* __restrict__ cnt, const int* __restrict__ csr,
           const float* __restrict__ eps, int layer, __half* __restrict__ h) {
    int warp = (blockIdx.x * blockDim.x + threadIdx.x) >> 5;
    int lane = threadIdx.x & 31;
    if (warp >= N_NODES) return;
    int base = off[warp];
    int deg  = cnt[warp];

    float2 acc = make_float2(0.f, 0.f);
    for (int c = 0; c < deg; c += 32) {
        int rem = deg - c;
        int m = rem < 32 ? rem : 32;
        int myi = (lane < m) ? __ldg(&csr[base + c + lane]) : 0;
        for (int j = 0; j < m; j++) {
            int s = __shfl_sync(0xffffffffu, myi, j);
            __half2 v = *(const __half2*)(x + (size_t)s * CC + lane * 2);
            float2 f = __half22float2(v);
            acc.x += f.x; acc.y += f.y;
        }
    }
    float e = 1.0f + __ldg(&eps[layer]);
    float2 xv = __half22float2(*(const __half2*)(x + (size_t)warp * CC + lane * 2));
    acc.x = fmaf(e, xv.x, acc.x);
    acc.y = fmaf(e, xv.y, acc.y);
    *(__half2*)(h + (size_t)warp * CC + lane * 2) = __floats2half2_rn(acc.x, acc.y);
}

// ---------------- MLP via mma.sync tf32 (HMMA) ------------------------------
// 256 threads = 8 warps; block tile = 128 rows x 64 cols, K = 64.
// Input h fp16; output fp16 (intermediate layers) or fp32 (final layer).

#define AP 68
#define WP 72
#define SF_C1 0
#define SF_C2 64
#define SF_SG 128
#define SF_ST 192
#define SF_A  256
#define SF_W1 (SF_A + 128 * AP)
#define SF_W2 (SF_W1 + 64 * WP)
#define SF_TOT (SF_W2 + 64 * WP)

__global__ void __launch_bounds__(256)
mlp_tc_kernel(const __half* __restrict__ h, float* __restrict__ outf,
              __half* __restrict__ outh, int out_half,
              const float* __restrict__ W1, const float* __restrict__ b1,
              const float* __restrict__ g1, const float* __restrict__ be1,
              const float* __restrict__ W2, const float* __restrict__ b2,
              const float* __restrict__ g2, const float* __restrict__ be2,
              const float* __restrict__ bng, const float* __restrict__ bnb,
              int do_relu) {
    extern __shared__ float smem[];
    float*    sc1 = smem + SF_C1;
    float*    sc2 = smem + SF_C2;
    float*    ssg = smem + SF_SG;
    float*    sst = smem + SF_ST;
    uint32_t* sA  = (uint32_t*)(smem + SF_A);
    uint32_t* sW1 = (uint32_t*)(smem + SF_W1);
    uint32_t* sW2 = (uint32_t*)(smem + SF_W2);
    const float bns = 0.999995000037f;  // 1/sqrt(1+1e-5)

    int tid = threadIdx.x;

    if (tid < 64) {
        sc1[tid] = b1[tid] * (g1[tid] * bns) + be1[tid];
        sc2[tid] = b2[tid] * (g2[tid] * bns) + be2[tid];
        ssg[tid] = bng[tid] * bns;
        sst[tid] = bnb[tid];
    }

    for (int idx = tid; idx < 4096; idx += 256) {
        int k = idx >> 6, n = idx & 63;
        sW1[k * WP + n] = f2tf32(W1[idx] * (g1[n] * bns));
        sW2[k * WP + n] = f2tf32(W2[idx] * (g2[n] * bns));
    }

    int rowbase = blockIdx.x * 128;
    for (int idx = tid; idx < 2048; idx += 256) {
        int r = idx >> 4, k4 = idx & 15;
        int gr = rowbase + r;
        float2 f01 = make_float2(0.f, 0.f), f23 = make_float2(0.f, 0.f);
        if (gr < N_NODES) {
            const __half2* hp = (const __half2*)(h + (size_t)gr * CC + k4 * 4);
            f01 = __half22float2(hp[0]);
            f23 = __half22float2(hp[1]);
        }
        uint32_t* p = &sA[r * AP + k4 * 4];
        p[0] = f2tf32(f01.x); p[1] = f2tf32(f01.y);
        p[2] = f2tf32(f23.x); p[3] = f2tf32(f23.y);
    }
    __syncthreads();

    int lane = tid & 31, warp = tid >> 5;
    int g = lane >> 2, c = lane & 3;
    int rb = warp * 16;

    float acc[8][4];

    #pragma unroll
    for (int nt = 0; nt < 8; nt++)
        #pragma unroll
        for (int i = 0; i < 4; i++) acc[nt][i] = 0.f;

    #pragma unroll
    for (int ks = 0; ks < 8; ks++) {
        int k0 = ks * 8;
        uint32_t a0 = sA[(rb + g)     * AP + k0 + c];
        uint32_t a1 = sA[(rb + g + 8) * AP + k0 + c];
        uint32_t a2 = sA[(rb + g)     * AP + k0 + c + 4];
        uint32_t a3 = sA[(rb + g + 8) * AP + k0 + c + 4];
        #pragma unroll
        for (int nt = 0; nt < 8; nt++) {
            uint32_t b0  = sW1[(k0 + c)     * WP + nt * 8 + g];
            uint32_t b1r = sW1[(k0 + c + 4) * WP + nt * 8 + g];
            mma_tf32(acc[nt], a0, a1, a2, a3, b0, b1r);
        }
    }

    #pragma unroll
    for (int nt = 0; nt < 8; nt++) {
        int j0 = nt * 8 + 2 * c;
        float w00 = fmaxf(acc[nt][0] + sc1[j0],     0.f);
        float w01 = fmaxf(acc[nt][1] + sc1[j0 + 1], 0.f);
        float w10 = fmaxf(acc[nt][2] + sc1[j0],     0.f);
        float w11 = fmaxf(acc[nt][3] + sc1[j0 + 1], 0.f);
        uint2 lo = make_uint2(f2tf32(w00), f2tf32(w01));
        uint2 hi = make_uint2(f2tf32(w10), f2tf32(w11));
        *(uint2*)&sA[(rb + g)     * AP + j0] = lo;
        *(uint2*)&sA[(rb + g + 8) * AP + j0] = hi;
    }
    __syncwarp();

    #pragma unroll
    for (int nt = 0; nt < 8; nt++)
        #pragma unroll
        for (int i = 0; i < 4; i++) acc[nt][i] = 0.f;

    #pragma unroll
    for (int ks = 0; ks < 8; ks++) {
        int k0 = ks * 8;
        uint32_t a0 = sA[(rb + g)     * AP + k0 + c];
        uint32_t a1 = sA[(rb + g + 8) * AP + k0 + c];
        uint32_t a2 = sA[(rb + g)     * AP + k0 + c + 4];
        uint32_t a3 = sA[(rb + g + 8) * AP + k0 + c + 4];
        #pragma unroll
        for (int nt = 0; nt < 8; nt++) {
            uint32_t b0  = sW2[(k0 + c)     * WP + nt * 8 + g];
            uint32_t b1r = sW2[(k0 + c + 4) * WP + nt * 8 + g];
            mma_tf32(acc[nt], a0, a1, a2, a3, b0, b1r);
        }
    }

    int r0 = rowbase + rb + g;
    int r1 = r0 + 8;
    #pragma unroll
    for (int nt = 0; nt < 8; nt++) {
        int j0 = nt * 8 + 2 * c;
        float s0 = ssg[j0], s1 = ssg[j0 + 1];
        float t0 = sst[j0], t1 = sst[j0 + 1];
        float2 o0, o1;
        o0.x = s0 * fmaxf(acc[nt][0] + sc2[j0],     0.f) + t0;
        o0.y = s1 * fmaxf(acc[nt][1] + sc2[j0 + 1], 0.f) + t1;
        o1.x = s0 * fmaxf(acc[nt][2] + sc2[j0],     0.f) + t0;
        o1.y = s1 * fmaxf(acc[nt][3] + sc2[j0 + 1], 0.f) + t1;
        if (do_relu) {
            o0.x = fmaxf(o0.x, 0.f); o0.y = fmaxf(o0.y, 0.f);
            o1.x = fmaxf(o1.x, 0.f); o1.y = fmaxf(o1.y, 0.f);
        }
        if (out_half) {
            if (r0 < N_NODES)
                *(__half2*)(outh + (size_t)r0 * CC + j0) = __floats2half2_rn(o0.x, o0.y);
            if (r1 < N_NODES)
                *(__half2*)(outh + (size_t)r1 * CC + j0) = __floats2half2_rn(o1.x, o1.y);
        } else {
            if (r0 < N_NODES) *(float2*)(outf + (size_t)r0 * CC + j0) = o0;
            if (r1 < N_NODES) *(float2*)(outf + (size_t)r1 * CC + j0) = o1;
        }
    }
}

extern "C" void kernel_launch(void* const* d_in, const int* in_sizes, int n_in,
                              void* d_out, int out_size) {
    const float* x   = (const float*)d_in[0];
    const int*   ei  = (const int*)d_in[1];
    const float* eps = (const float*)d_in[2];
    const float* W1  = (const float*)d_in[3];
    const float* b1  = (const float*)d_in[4];
    const float* g1  = (const float*)d_in[5];
    const float* be1 = (const float*)d_in[6];
    const float* W2  = (const float*)d_in[7];
    const float* b2  = (const float*)d_in[8];
    const float* g2  = (const float*)d_in[9];
    const float* be2 = (const float*)d_in[10];
    const float* bng = (const float*)d_in[11];
    const float* bnb = (const float*)d_in[12];
    float* out = (float*)d_out;

    __half *hb, *xh0, *xha, *xhb;
    int *cnt, *off, *cur, *csr, *bsum;
    cudaGetSymbolAddress((void**)&hb,   g_h);
    cudaGetSymbolAddress((void**)&xh0,  g_xh0);
    cudaGetSymbolAddress((void**)&xha,  g_xha);
    cudaGetSymbolAddress((void**)&xhb,  g_xhb);
    cudaGetSymbolAddress((void**)&cnt,  g_cnt);
    cudaGetSymbolAddress((void**)&off,  g_off);
    cudaGetSymbolAddress((void**)&cur,  g_cur);
    cudaGetSymbolAddress((void**)&csr,  g_csr);
    cudaGetSymbolAddress((void**)&bsum, g_bsum);

    const int smem_bytes = SF_TOT * 4;  // 72704
    cudaFuncSetAttribute(mlp_tc_kernel,
                         cudaFuncAttributeMaxDynamicSharedMemorySize, smem_bytes);

    const int eblk = (N_EDGES + 255) / 256;
    const int nblk = (N_NODES + 255) / 256;
    const int cblk = (N_NODES * CC / 4 + 255) / 256;    // 6250
    const int mlp_blocks = (N_NODES + 127) / 128;       // 782
    const int agg_blocks = (N_NODES * 32 + 255) / 256;  // 12500

    // CSR build (edge_index constant across layers) + x fp16 conversion.
    cudaMemsetAsync(cnt, 0, N_NODES * sizeof(int));
    x2h_kernel<<<cblk, 256>>>(x, xh0);
    hist_kernel<<<eblk, 256>>>(ei, cnt);
    scan_blocks_kernel<<<N_SCANB, SCAN_BLK>>>(cnt, off, bsum);
    scan_bsum_kernel<<<1, 128>>>(bsum);
    add_off_kernel<<<nblk, 256>>>(off, bsum, cur);
    fill_csr_kernel<<<eblk, 256>>>(ei, cur, csr);

    const __half* xin = xh0;
    __half* houts[NL] = {xha, xhb, nullptr};
    for (int l = 0; l < NL; l++) {
        // MEASUREMENT: agg launched twice (idempotent). dur delta vs the
        // 239.7us baseline = 3 x T_agg. Next round removes the duplicate.
        agg_kernel<<<agg_blocks, 256>>>(xin, off, cnt, csr, eps, l, hb);
        agg_kernel<<<agg_blocks, 256>>>(xin, off, cnt, csr, eps, l, hb);
        int is_half = (l < NL - 1) ? 1 : 0;
        mlp_tc_kernel<<<mlp_blocks, 256, smem_bytes>>>(
            hb, out, houts[l], is_half,
            W1 + l * 4096, b1 + l * 64, g1 + l * 64, be1 + l * 64,
            W2 + l * 4096, b2 + l * 64, g2 + l * 64, be2 + l * 64,
            bng + l * 64, bnb + l * 64, (l < NL - 1) ? 1 : 0);
        xin = houts[l];
    }
}

// round 15
// speedup vs baseline: 1.4716x; 1.4716x over previous
#include <cuda_runtime.h>
#include <cuda_fp16.h>
#include <cstdint>

#define N_NODES 100000
#define N_EDGES 1600000
#define CC 64
#define NL 3
#define SCAN_BLK 1024
#define N_SCANB ((N_NODES + SCAN_BLK - 1) / SCAN_BLK)   // 98

// Static device scratch (allowed).
__device__ __half g_h  [N_NODES * CC];          // agg output (fp16 ~ tf32 mantissa)
__device__ __half g_xh0[N_NODES * CC];          // fp16 copy of input x
__device__ __half g_xha[N_NODES * CC];          // layer-0 output (fp16)
__device__ __half g_xhb[N_NODES * CC];          // layer-1 output (fp16)
__device__ int    g_cnt[N_NODES];
__device__ int    g_off[N_NODES];
__device__ int    g_cur[N_NODES];
__device__ int    g_csr[N_EDGES];
__device__ int    g_bsum[N_SCANB + 1];
__device__ float  g_wf[NL * 2 * 4608];          // folded tf32 weights, smem image
__device__ float  g_cv[NL * 256];               // folded constants (c1,c2,sg,st)

// ---------------- tf32 mma helpers (sm_80+ baseline — no 'a' features) -----

__device__ __forceinline__ uint32_t f2tf32(float f) {
    uint32_t r;
    asm("cvt.rna.tf32.f32 %0, %1;" : "=r"(r) : "f"(f));
    return r;
}

__device__ __forceinline__ void mma_tf32(float* d,
                                         uint32_t a0, uint32_t a1,
                                         uint32_t a2, uint32_t a3,
                                         uint32_t b0, uint32_t b1) {
    asm volatile(
        "mma.sync.aligned.m16n8k8.row.col.f32.tf32.tf32.f32 "
        "{%0,%1,%2,%3}, {%4,%5,%6,%7}, {%8,%9}, {%0,%1,%2,%3};"
        : "+f"(d[0]), "+f"(d[1]), "+f"(d[2]), "+f"(d[3])
        : "r"(a0), "r"(a1), "r"(a2), "r"(a3), "r"(b0), "r"(b1));
}

// ---------------- one-time weight folding (per launch) ----------------------
// Produces the exact smem image the MLP kernel consumes:
//   wf[l] = [ W1f 64x72 | W2f 64x72 ]  (tf32 bit patterns stored as float)
//   cv[l] = [ c1[64] | c2[64] | sg[64] | st[64] ]

__global__ void wconv_kernel(const float* __restrict__ W1, const float* __restrict__ b1,
                             const float* __restrict__ g1, const float* __restrict__ be1,
                             const float* __restrict__ W2, const float* __restrict__ b2,
                             const float* __restrict__ g2, const float* __restrict__ be2,
                             const float* __restrict__ bng, const float* __restrict__ bnb,
                             float* __restrict__ wf, float* __restrict__ cv) {
    const float bns = 0.999995000037f;  // 1/sqrt(1+1e-5)
    int l = blockIdx.x;
    int tid = threadIdx.x;

    if (tid < 64) {
        int j = tid;
        cv[l * 256 + j]       = b1[l * 64 + j] * (g1[l * 64 + j] * bns) + be1[l * 64 + j];
        cv[l * 256 + 64 + j]  = b2[l * 64 + j] * (g2[l * 64 + j] * bns) + be2[l * 64 + j];
        cv[l * 256 + 128 + j] = bng[l * 64 + j] * bns;
        cv[l * 256 + 192 + j] = bnb[l * 64 + j];
    }

    float* wl = wf + l * 2 * 4608;
    for (int idx = tid; idx < 4096; idx += 256) {
        int k = idx >> 6, n = idx & 63;
        wl[k * 72 + n] =
            __uint_as_float(f2tf32(W1[l * 4096 + idx] * (g1[l * 64 + n] * bns)));
        wl[4608 + k * 72 + n] =
            __uint_as_float(f2tf32(W2[l * 4096 + idx] * (g2[l * 64 + n] * bns)));
    }
    // zero the pitch padding (n = 64..71)
    for (int idx = tid; idx < 512; idx += 256) {
        int k = idx >> 3, n = 64 + (idx & 7);
        wl[k * 72 + n] = 0.f;
        wl[4608 + k * 72 + n] = 0.f;
    }
}

// ---------------- CSR build (once per launch) -------------------------------

__global__ void hist_kernel(const int* __restrict__ ei, int* __restrict__ cnt) {
    int e = blockIdx.x * blockDim.x + threadIdx.x;
    if (e < N_EDGES) atomicAdd(&cnt[ei[N_EDGES + e]], 1);
}

__global__ void scan_blocks_kernel(const int* __restrict__ cnt,
                                   int* __restrict__ off, int* __restrict__ bsum) {
    __shared__ int sm[SCAN_BLK];
    int gid = blockIdx.x * SCAN_BLK + threadIdx.x;
    int v = (gid < N_NODES) ? cnt[gid] : 0;
    sm[threadIdx.x] = v;
    __syncthreads();
    #pragma unroll
    for (int o = 1; o < SCAN_BLK; o <<= 1) {
        int t = (threadIdx.x >= o) ? sm[threadIdx.x - o] : 0;
        __syncthreads();
        sm[threadIdx.x] += t;
        __syncthreads();
    }
    if (gid < N_NODES) off[gid] = sm[threadIdx.x] - v;
    if (threadIdx.x == SCAN_BLK - 1) bsum[blockIdx.x] = sm[threadIdx.x];
}

__global__ void scan_bsum_kernel(int* __restrict__ bsum) {
    __shared__ int sm[128];
    int t = threadIdx.x;
    int v = (t < N_SCANB) ? bsum[t] : 0;
    sm[t] = v;
    __syncthreads();
    #pragma unroll
    for (int o = 1; o < 128; o <<= 1) {
        int u = (t >= o) ? sm[t - o] : 0;
        __syncthreads();
        sm[t] += u;
        __syncthreads();
    }
    if (t < N_SCANB) bsum[t] = sm[t] - v;
}

__global__ void add_off_kernel(int* __restrict__ off, const int* __restrict__ bsum,
                               int* __restrict__ cur) {
    int gid = blockIdx.x * blockDim.x + threadIdx.x;
    if (gid < N_NODES) {
        int v = off[gid] + bsum[gid / SCAN_BLK];
        off[gid] = v;
        cur[gid] = v;
    }
}

__global__ void fill_csr_kernel(const int* __restrict__ ei,
                                int* __restrict__ cur, int* __restrict__ csr) {
    int e = blockIdx.x * blockDim.x + threadIdx.x;
    if (e < N_EDGES) {
        int d = ei[N_EDGES + e];
        int p = atomicAdd(&cur[d], 1);
        csr[p] = ei[e];
    }
}

// ---------------- x fp32 -> fp16 (once per launch) --------------------------

__global__ void x2h_kernel(const float* __restrict__ x, __half* __restrict__ xh) {
    int i = blockIdx.x * blockDim.x + threadIdx.x;
    if (i >= N_NODES * CC / 4) return;
    float4 v = ((const float4*)x)[i];
    __half2* p = (__half2*)xh + i * 2;
    p[0] = __floats2half2_rn(v.x, v.y);
    p[1] = __floats2half2_rn(v.z, v.w);
}

// ---------------- Aggregation: warp-per-node, fp16 gather, fp32 accum -------

__global__ void __launch_bounds__(256)
agg_kernel(const __half* __restrict__ x, const int* __restrict__ off,
           const int* __restrict__ cnt, const int* __restrict__ csr,
           const float* __restrict__ eps, int layer, __half* __restrict__ h) {
    int warp = (blockIdx.x * blockDim.x + threadIdx.x) >> 5;
    int lane = threadIdx.x & 31;
    if (warp >= N_NODES) return;
    int base = off[warp];
    int deg  = cnt[warp];

    float2 acc = make_float2(0.f, 0.f);
    for (int c = 0; c < deg; c += 32) {
        int rem = deg - c;
        int m = rem < 32 ? rem : 32;
        int myi = (lane < m) ? __ldg(&csr[base + c + lane]) : 0;
        for (int j = 0; j < m; j++) {
            int s = __shfl_sync(0xffffffffu, myi, j);
            __half2 v = *(const __half2*)(x + (size_t)s * CC + lane * 2);
            float2 f = __half22float2(v);
            acc.x += f.x; acc.y += f.y;
        }
    }
    float e = 1.0f + __ldg(&eps[layer]);
    float2 xv = __half22float2(*(const __half2*)(x + (size_t)warp * CC + lane * 2));
    acc.x = fmaf(e, xv.x, acc.x);
    acc.y = fmaf(e, xv.y, acc.y);
    *(__half2*)(h + (size_t)warp * CC + lane * 2) = __floats2half2_rn(acc.x, acc.y);
}

// ---------------- MLP via mma.sync tf32 (HMMA) ------------------------------
// 256 threads = 8 warps; block tile = 128 rows x 64 cols, K = 64.
// Prologue is now a pure float4 copy of the prefolded weight/constant image.

#define AP 68
#define WP 72
#define SF_C1 0
#define SF_C2 64
#define SF_SG 128
#define SF_ST 192
#define SF_A  256
#define SF_W1 (SF_A + 128 * AP)
#define SF_W2 (SF_W1 + 64 * WP)
#define SF_TOT (SF_W2 + 64 * WP)

__global__ void __launch_bounds__(256)
mlp_tc_kernel(const __half* __restrict__ h, float* __restrict__ outf,
              __half* __restrict__ outh, int out_half,
              const float4* __restrict__ wf_l, const float4* __restrict__ cv_l,
              int do_relu) {
    extern __shared__ float smem[];
    float*    sc1 = smem + SF_C1;
    float*    sc2 = smem + SF_C2;
    float*    ssg = smem + SF_SG;
    float*    sst = smem + SF_ST;
    uint32_t* sA  = (uint32_t*)(smem + SF_A);
    uint32_t* sW1 = (uint32_t*)(smem + SF_W1);
    uint32_t* sW2 = (uint32_t*)(smem + SF_W2);

    int tid = threadIdx.x;

    // constants: 256 floats = 64 float4
    if (tid < 64) ((float4*)smem)[tid] = cv_l[tid];

    // weights: W1f|W2f contiguous smem image, 9216 floats = 2304 float4
    {
        float4* dst = (float4*)(smem + SF_W1);
        #pragma unroll
        for (int i = 0; i < 9; i++) {
            int idx = tid + i * 256;
            dst[idx] = wf_l[idx];
        }
    }

    int rowbase = blockIdx.x * 128;
    for (int idx = tid; idx < 2048; idx += 256) {
        int r = idx >> 4, k4 = idx & 15;
        int gr = rowbase + r;
        float2 f01 = make_float2(0.f, 0.f), f23 = make_float2(0.f, 0.f);
        if (gr < N_NODES) {
            const __half2* hp = (const __half2*)(h + (size_t)gr * CC + k4 * 4);
            f01 = __half22float2(hp[0]);
            f23 = __half22float2(hp[1]);
        }
        uint32_t* p = &sA[r * AP + k4 * 4];
        p[0] = f2tf32(f01.x); p[1] = f2tf32(f01.y);
        p[2] = f2tf32(f23.x); p[3] = f2tf32(f23.y);
    }
    __syncthreads();

    int lane = tid & 31, warp = tid >> 5;
    int g = lane >> 2, c = lane & 3;
    int rb = warp * 16;

    float acc[8][4];

    #pragma unroll
    for (int nt = 0; nt < 8; nt++)
        #pragma unroll
        for (int i = 0; i < 4; i++) acc[nt][i] = 0.f;

    #pragma unroll
    for (int ks = 0; ks < 8; ks++) {
        int k0 = ks * 8;
        uint32_t a0 = sA[(rb + g)     * AP + k0 + c];
        uint32_t a1 = sA[(rb + g + 8) * AP + k0 + c];
        uint32_t a2 = sA[(rb + g)     * AP + k0 + c + 4];
        uint32_t a3 = sA[(rb + g + 8) * AP + k0 + c + 4];
        #pragma unroll
        for (int nt = 0; nt < 8; nt++) {
            uint32_t b0  = sW1[(k0 + c)     * WP + nt * 8 + g];
            uint32_t b1r = sW1[(k0 + c + 4) * WP + nt * 8 + g];
            mma_tf32(acc[nt], a0, a1, a2, a3, b0, b1r);
        }
    }

    #pragma unroll
    for (int nt = 0; nt < 8; nt++) {
        int j0 = nt * 8 + 2 * c;
        float w00 = fmaxf(acc[nt][0] + sc1[j0],     0.f);
        float w01 = fmaxf(acc[nt][1] + sc1[j0 + 1], 0.f);
        float w10 = fmaxf(acc[nt][2] + sc1[j0],     0.f);
        float w11 = fmaxf(acc[nt][3] + sc1[j0 + 1], 0.f);
        uint2 lo = make_uint2(f2tf32(w00), f2tf32(w01));
        uint2 hi = make_uint2(f2tf32(w10), f2tf32(w11));
        *(uint2*)&sA[(rb + g)     * AP + j0] = lo;
        *(uint2*)&sA[(rb + g + 8) * AP + j0] = hi;
    }
    __syncwarp();

    #pragma unroll
    for (int nt = 0; nt < 8; nt++)
        #pragma unroll
        for (int i = 0; i < 4; i++) acc[nt][i] = 0.f;

    #pragma unroll
    for (int ks = 0; ks < 8; ks++) {
        int k0 = ks * 8;
        uint32_t a0 = sA[(rb + g)     * AP + k0 + c];
        uint32_t a1 = sA[(rb + g + 8) * AP + k0 + c];
        uint32_t a2 = sA[(rb + g)     * AP + k0 + c + 4];
        uint32_t a3 = sA[(rb + g + 8) * AP + k0 + c + 4];
        #pragma unroll
        for (int nt = 0; nt < 8; nt++) {
            uint32_t b0  = sW2[(k0 + c)     * WP + nt * 8 + g];
            uint32_t b1r = sW2[(k0 + c + 4) * WP + nt * 8 + g];
            mma_tf32(acc[nt], a0, a1, a2, a3, b0, b1r);
        }
    }

    int r0 = rowbase + rb + g;
    int r1 = r0 + 8;
    #pragma unroll
    for (int nt = 0; nt < 8; nt++) {
        int j0 = nt * 8 + 2 * c;
        float s0 = ssg[j0], s1 = ssg[j0 + 1];
        float t0 = sst[j0], t1 = sst[j0 + 1];
        float2 o0, o1;
        o0.x = s0 * fmaxf(acc[nt][0] + sc2[j0],     0.f) + t0;
        o0.y = s1 * fmaxf(acc[nt][1] + sc2[j0 + 1], 0.f) + t1;
        o1.x = s0 * fmaxf(acc[nt][2] + sc2[j0],     0.f) + t0;
        o1.y = s1 * fmaxf(acc[nt][3] + sc2[j0 + 1], 0.f) + t1;
        if (do_relu) {
            o0.x = fmaxf(o0.x, 0.f); o0.y = fmaxf(o0.y, 0.f);
            o1.x = fmaxf(o1.x, 0.f); o1.y = fmaxf(o1.y, 0.f);
        }
        if (out_half) {
            if (r0 < N_NODES)
                *(__half2*)(outh + (size_t)r0 * CC + j0) = __floats2half2_rn(o0.x, o0.y);
            if (r1 < N_NODES)
                *(__half2*)(outh + (size_t)r1 * CC + j0) = __floats2half2_rn(o1.x, o1.y);
        } else {
            if (r0 < N_NODES) *(float2*)(outf + (size_t)r0 * CC + j0) = o0;
            if (r1 < N_NODES) *(float2*)(outf + (size_t)r1 * CC + j0) = o1;
        }
    }
}

extern "C" void kernel_launch(void* const* d_in, const int* in_sizes, int n_in,
                              void* d_out, int out_size) {
    const float* x   = (const float*)d_in[0];
    const int*   ei  = (const int*)d_in[1];
    const float* eps = (const float*)d_in[2];
    const float* W1  = (const float*)d_in[3];
    const float* b1  = (const float*)d_in[4];
    const float* g1  = (const float*)d_in[5];
    const float* be1 = (const float*)d_in[6];
    const float* W2  = (const float*)d_in[7];
    const float* b2  = (const float*)d_in[8];
    const float* g2  = (const float*)d_in[9];
    const float* be2 = (const float*)d_in[10];
    const float* bng = (const float*)d_in[11];
    const float* bnb = (const float*)d_in[12];
    float* out = (float*)d_out;

    __half *hb, *xh0, *xha, *xhb;
    int *cnt, *off, *cur, *csr, *bsum;
    float *wf, *cv;
    cudaGetSymbolAddress((void**)&hb,   g_h);
    cudaGetSymbolAddress((void**)&xh0,  g_xh0);
    cudaGetSymbolAddress((void**)&xha,  g_xha);
    cudaGetSymbolAddress((void**)&xhb,  g_xhb);
    cudaGetSymbolAddress((void**)&cnt,  g_cnt);
    cudaGetSymbolAddress((void**)&off,  g_off);
    cudaGetSymbolAddress((void**)&cur,  g_cur);
    cudaGetSymbolAddress((void**)&csr,  g_csr);
    cudaGetSymbolAddress((void**)&bsum, g_bsum);
    cudaGetSymbolAddress((void**)&wf,   g_wf);
    cudaGetSymbolAddress((void**)&cv,   g_cv);

    const int smem_bytes = SF_TOT * 4;  // 72704
    cudaFuncSetAttribute(mlp_tc_kernel,
                         cudaFuncAttributeMaxDynamicSharedMemorySize, smem_bytes);

    const int eblk = (N_EDGES + 255) / 256;
    const int nblk = (N_NODES + 255) / 256;
    const int cblk = (N_NODES * CC / 4 + 255) / 256;    // 6250
    const int mlp_blocks = (N_NODES + 127) / 128;       // 782
    const int agg_blocks = (N_NODES * 32 + 255) / 256;  // 12500

    // CSR build (edge_index constant across layers) + conversions.
    cudaMemsetAsync(cnt, 0, N_NODES * sizeof(int));
    x2h_kernel<<<cblk, 256>>>(x, xh0);
    wconv_kernel<<<NL, 256>>>(W1, b1, g1, be1, W2, b2, g2, be2, bng, bnb, wf, cv);
    hist_kernel<<<eblk, 256>>>(ei, cnt);
    scan_blocks_kernel<<<N_SCANB, SCAN_BLK>>>(cnt, off, bsum);
    scan_bsum_kernel<<<1, 128>>>(bsum);
    add_off_kernel<<<nblk, 256>>>(off, bsum, cur);
    fill_csr_kernel<<<eblk, 256>>>(ei, cur, csr);

    const __half* xin = xh0;
    __half* houts[NL] = {xha, xhb, nullptr};
    for (int l = 0; l < NL; l++) {
        agg_kernel<<<agg_blocks, 256>>>(xin, off, cnt, csr, eps, l, hb);
        int is_half = (l < NL - 1) ? 1 : 0;
        mlp_tc_kernel<<<mlp_blocks, 256, smem_bytes>>>(
            hb, out, houts[l], is_half,
            (const float4*)(wf + l * 2 * 4608), (const float4*)(cv + l * 256),
            (l < NL - 1) ? 1 : 0);
        xin = houts[l];
    }
}

// round 17
// speedup vs baseline: 1.5707x; 1.0673x over previous
#include <cuda_runtime.h>
#include <cuda_fp16.h>
#include <cstdint>

#define N_NODES 100000
#define N_EDGES 1600000
#define CC 64
#define NL 3
#define SCAN_BLK 1024
#define N_SCANB ((N_NODES + SCAN_BLK - 1) / SCAN_BLK)   // 98

// Static device scratch (allowed).
__device__ __half g_h  [N_NODES * CC];          // agg output (fp16)
__device__ __half g_xh0[N_NODES * CC];          // fp16 copy of input x
__device__ __half g_xha[N_NODES * CC];          // layer-0 output (fp16)
__device__ __half g_xhb[N_NODES * CC];          // layer-1 output (fp16)
__device__ int    g_cnt[N_NODES];
__device__ int    g_off[N_NODES];
__device__ int    g_cur[N_NODES];
__device__ int    g_csr[N_EDGES];
__device__ int    g_bsum[N_SCANB + 1];
__device__ __half g_wfh[NL * 2 * 4608];         // folded fp16 weights [n][k] pitch 72
__device__ float  g_cv[NL * 256];               // folded constants (c1,c2,sg,st)

// ---------------- fp16 mma helper (sm_80+ baseline) -------------------------

__device__ __forceinline__ void mma_f16(float* d,
                                        uint32_t a0, uint32_t a1,
                                        uint32_t a2, uint32_t a3,
                                        uint32_t b0, uint32_t b1) {
    asm volatile(
        "mma.sync.aligned.m16n8k16.row.col.f32.f16.f16.f32 "
        "{%0,%1,%2,%3}, {%4,%5,%6,%7}, {%8,%9}, {%0,%1,%2,%3};"
        : "+f"(d[0]), "+f"(d[1]), "+f"(d[2]), "+f"(d[3])
        : "r"(a0), "r"(a1), "r"(a2), "r"(a3), "r"(b0), "r"(b1));
}

// ---------------- one-time weight folding (per launch) ----------------------
// wfh[l] = [ W1f | W2f ], each [n=64][k=72 halves] (pad k 64..71 = 0), fp16.
// cv[l]  = [ c1[64] | c2[64] | sg[64] | st[64] ] fp32.

__global__ void wconv_kernel(const float* __restrict__ W1, const float* __restrict__ b1,
                             const float* __restrict__ g1, const float* __restrict__ be1,
                             const float* __restrict__ W2, const float* __restrict__ b2,
                             const float* __restrict__ g2, const float* __restrict__ be2,
                             const float* __restrict__ bng, const float* __restrict__ bnb,
                             __half* __restrict__ wfh, float* __restrict__ cv) {
    const float bns = 0.999995000037f;  // 1/sqrt(1+1e-5)
    int l = blockIdx.x;
    int tid = threadIdx.x;

    if (tid < 64) {
        int j = tid;
        cv[l * 256 + j]       = b1[l * 64 + j] * (g1[l * 64 + j] * bns) + be1[l * 64 + j];
        cv[l * 256 + 64 + j]  = b2[l * 64 + j] * (g2[l * 64 + j] * bns) + be2[l * 64 + j];
        cv[l * 256 + 128 + j] = bng[l * 64 + j] * bns;
        cv[l * 256 + 192 + j] = bnb[l * 64 + j];
    }

    __half* wlh = wfh + l * 2 * 4608;
    for (int idx = tid; idx < 4096; idx += 256) {
        int k = idx >> 6, n = idx & 63;
        wlh[n * 72 + k]        = __float2half(W1[l * 4096 + idx] * (g1[l * 64 + n] * bns));
        wlh[4608 + n * 72 + k] = __float2half(W2[l * 4096 + idx] * (g2[l * 64 + n] * bns));
    }
    for (int idx = tid; idx < 512; idx += 256) {
        int n = idx >> 3, k = 64 + (idx & 7);
        wlh[n * 72 + k] = __float2half(0.f);
        wlh[4608 + n * 72 + k] = __float2half(0.f);
    }
}

// ---------------- CSR build (once per launch) -------------------------------

__global__ void hist_kernel(const int* __restrict__ ei, int* __restrict__ cnt) {
    int e = blockIdx.x * blockDim.x + threadIdx.x;
    if (e < N_EDGES) atomicAdd(&cnt[ei[N_EDGES + e]], 1);
}

__global__ void scan_blocks_kernel(const int* __restrict__ cnt,
                                   int* __restrict__ off, int* __restrict__ bsum) {
    __shared__ int sm[SCAN_BLK];
    int gid = blockIdx.x * SCAN_BLK + threadIdx.x;
    int v = (gid < N_NODES) ? cnt[gid] : 0;
    sm[threadIdx.x] = v;
    __syncthreads();
    #pragma unroll
    for (int o = 1; o < SCAN_BLK; o <<= 1) {
        int t = (threadIdx.x >= o) ? sm[threadIdx.x - o] : 0;
        __syncthreads();
        sm[threadIdx.x] += t;
        __syncthreads();
    }
    if (gid < N_NODES) off[gid] = sm[threadIdx.x] - v;
    if (threadIdx.x == SCAN_BLK - 1) bsum[blockIdx.x] = sm[threadIdx.x];
}

__global__ void scan_bsum_kernel(int* __restrict__ bsum) {
    __shared__ int sm[128];
    int t = threadIdx.x;
    int v = (t < N_SCANB) ? bsum[t] : 0;
    sm[t] = v;
    __syncthreads();
    #pragma unroll
    for (int o = 1; o < 128; o <<= 1) {
        int u = (t >= o) ? sm[t - o] : 0;
        __syncthreads();
        sm[t] += u;
        __syncthreads();
    }
    if (t < N_SCANB) bsum[t] = sm[t] - v;
}

__global__ void add_off_kernel(int* __restrict__ off, const int* __restrict__ bsum,
                               int* __restrict__ cur) {
    int gid = blockIdx.x * blockDim.x + threadIdx.x;
    if (gid < N_NODES) {
        int v = off[gid] + bsum[gid / SCAN_BLK];
        off[gid] = v;
        cur[gid] = v;
    }
}

__global__ void fill_csr_kernel(const int* __restrict__ ei,
                                int* __restrict__ cur, int* __restrict__ csr) {
    int e = blockIdx.x * blockDim.x + threadIdx.x;
    if (e < N_EDGES) {
        int d = ei[N_EDGES + e];
        int p = atomicAdd(&cur[d], 1);
        csr[p] = ei[e];
    }
}

// ---------------- x fp32 -> fp16 (once per launch) --------------------------

__global__ void x2h_kernel(const float* __restrict__ x, __half* __restrict__ xh) {
    int i = blockIdx.x * blockDim.x + threadIdx.x;
    if (i >= N_NODES * CC / 4) return;
    float4 v = ((const float4*)x)[i];
    __half2* p = (__half2*)xh + i * 2;
    p[0] = __floats2half2_rn(v.x, v.y);
    p[1] = __floats2half2_rn(v.z, v.w);
}

// ---------------- Aggregation: warp-per-node, fp16 gather, fp32 accum -------

__global__ void __launch_bounds__(256)
agg_kernel(const __half* __restrict__ x, const int* __restrict__ off,
           const int* __restrict__ cnt, const int* __restrict__ csr,
           const float* __restrict__ eps, int layer, __half* __restrict__ h) {
    int warp = (blockIdx.x * blockDim.x + threadIdx.x) >> 5;
    int lane = threadIdx.x & 31;
    if (warp >= N_NODES) return;
    int base = off[warp];
    int deg  = cnt[warp];

    float2 acc = make_float2(0.f, 0.f);
    for (int c = 0; c < deg; c += 32) {
        int rem = deg - c;
        int m = rem < 32 ? rem : 32;
        int myi = (lane < m) ? __ldg(&csr[base + c + lane]) : 0;
        for (int j = 0; j < m; j++) {
            int s = __shfl_sync(0xffffffffu, myi, j);
            __half2 v = *(const __half2*)(x + (size_t)s * CC + lane * 2);
            float2 f = __half22float2(v);
            acc.x += f.x; acc.y += f.y;
        }
    }
    float e = 1.0f + __ldg(&eps[layer]);
    float2 xv = __half22float2(*(const __half2*)(x + (size_t)warp * CC + lane * 2));
    acc.x = fmaf(e, xv.x, acc.x);
    acc.y = fmaf(e, xv.y, acc.y);
    *(__half2*)(h + (size_t)warp * CC + lane * 2) = __floats2half2_rn(acc.x, acc.y);
}

// ---------------- MLP via mma.sync fp16 m16n8k16 ----------------------------
// 256 threads = 8 warps; block tile = 128 rows x 64 cols, K = 64 (4 k-steps).
// A and weights fp16 in smem (pitch 72 halves, conflict-free fragments);
// fp32 accumulate; epilogue identical math to tf32 version.

// smem byte offsets
#define SB_CV 0        // 256 floats = 1024B
#define SB_A  1024     // 128*72 halves = 18432B
#define SB_W  19456    // 2*4608 halves = 18432B (W1 | W2)
#define SB_TOT 37888

__global__ void __launch_bounds__(256)
mlp_tc_kernel(const __half* __restrict__ h, float* __restrict__ outf,
              __half* __restrict__ outh, int out_half,
              const uint4* __restrict__ wf_l, const float4* __restrict__ cv_l,
              int do_relu) {
    extern __shared__ char smem[];
    float*  scv = (float*)(smem + SB_CV);
    __half* sAh = (__half*)(smem + SB_A);
    __half* sW1h = (__half*)(smem + SB_W);
    __half* sW2h = sW1h + 4608;

    int tid = threadIdx.x;

    // constants: 64 float4
    if (tid < 64) ((float4*)scv)[tid] = cv_l[tid];
    float* sc1 = scv;
    float* sc2 = scv + 64;
    float* ssg = scv + 128;
    float* sst = scv + 192;

    // weights: 18432B = 1152 uint4
    {
        uint4* dst = (uint4*)(smem + SB_W);
        for (int idx = tid; idx < 1152; idx += 256) dst[idx] = wf_l[idx];
    }

    // A tile: pure fp16 copy, no conversion.
    int rowbase = blockIdx.x * 128;
    for (int idx = tid; idx < 2048; idx += 256) {
        int r = idx >> 4, k4 = idx & 15;
        int gr = rowbase + r;
        uint2 v = make_uint2(0u, 0u);
        if (gr < N_NODES) v = *(const uint2*)(h + (size_t)gr * CC + k4 * 4);
        *(uint2*)(sAh + r * 72 + k4 * 4) = v;
    }
    __syncthreads();

    int lane = tid & 31, warp = tid >> 5;
    int g = lane >> 2, c = lane & 3;
    int rb = warp * 16;

    float acc[8][4];

    // ---- GEMM 1 ----
    #pragma unroll
    for (int nt = 0; nt < 8; nt++)
        #pragma unroll
        for (int i = 0; i < 4; i++) acc[nt][i] = 0.f;

    #pragma unroll
    for (int ks = 0; ks < 4; ks++) {
        int k0 = ks * 16;
        const __half* ar = sAh + (rb + g) * 72 + k0 + 2 * c;
        uint32_t a0 = *(const uint32_t*)(ar);
        uint32_t a1 = *(const uint32_t*)(ar + 8 * 72);
        uint32_t a2 = *(const uint32_t*)(ar + 8);
        uint32_t a3 = *(const uint32_t*)(ar + 8 * 72 + 8);
        #pragma unroll
        for (int nt = 0; nt < 8; nt++) {
            const __half* br = sW1h + (nt * 8 + g) * 72 + k0 + 2 * c;
            uint32_t b0 = *(const uint32_t*)(br);
            uint32_t b1 = *(const uint32_t*)(br + 8);
            mma_f16(acc[nt], a0, a1, a2, a3, b0, b1);
        }
    }

    // Epilogue 1: ReLU(z + c1) -> fp16 -> back into sAh (warp-local rows).
    #pragma unroll
    for (int nt = 0; nt < 8; nt++) {
        int j0 = nt * 8 + 2 * c;
        float w00 = fmaxf(acc[nt][0] + sc1[j0],     0.f);
        float w01 = fmaxf(acc[nt][1] + sc1[j0 + 1], 0.f);
        float w10 = fmaxf(acc[nt][2] + sc1[j0],     0.f);
        float w11 = fmaxf(acc[nt][3] + sc1[j0 + 1], 0.f);
        *(__half2*)(sAh + (rb + g) * 72 + j0)     = __floats2half2_rn(w00, w01);
        *(__half2*)(sAh + (rb + g + 8) * 72 + j0) = __floats2half2_rn(w10, w11);
    }
    __syncwarp();

    // ---- GEMM 2 ----
    #pragma unroll
    for (int nt = 0; nt < 8; nt++)
        #pragma unroll
        for (int i = 0; i < 4; i++) acc[nt][i] = 0.f;

    #pragma unroll
    for (int ks = 0; ks < 4; ks++) {
        int k0 = ks * 16;
        const __half* ar = sAh + (rb + g) * 72 + k0 + 2 * c;
        uint32_t a0 = *(const uint32_t*)(ar);
        uint32_t a1 = *(const uint32_t*)(ar + 8 * 72);
        uint32_t a2 = *(const uint32_t*)(ar + 8);
        uint32_t a3 = *(const uint32_t*)(ar + 8 * 72 + 8);
        #pragma unroll
        for (int nt = 0; nt < 8; nt++) {
            const __half* br = sW2h + (nt * 8 + g) * 72 + k0 + 2 * c;
            uint32_t b0 = *(const uint32_t*)(br);
            uint32_t b1 = *(const uint32_t*)(br + 8);
            mma_f16(acc[nt], a0, a1, a2, a3, b0, b1);
        }
    }

    // Epilogue 2: ReLU(z + c2), outer BN, optional ReLU, store.
    int r0 = rowbase + rb + g;
    int r1 = r0 + 8;
    #pragma unroll
    for (int nt = 0; nt < 8; nt++) {
        int j0 = nt * 8 + 2 * c;
        float s0 = ssg[j0], s1 = ssg[j0 + 1];
        float t0 = sst[j0], t1 = sst[j0 + 1];
        float2 o0, o1;
        o0.x = s0 * fmaxf(acc[nt][0] + sc2[j0],     0.f) + t0;
        o0.y = s1 * fmaxf(acc[nt][1] + sc2[j0 + 1], 0.f) + t1;
        o1.x = s0 * fmaxf(acc[nt][2] + sc2[j0],     0.f) + t0;
        o1.y = s1 * fmaxf(acc[nt][3] + sc2[j0 + 1], 0.f) + t1;
        if (do_relu) {
            o0.x = fmaxf(o0.x, 0.f); o0.y = fmaxf(o0.y, 0.f);
            o1.x = fmaxf(o1.x, 0.f); o1.y = fmaxf(o1.y, 0.f);
        }
        if (out_half) {
            if (r0 < N_NODES)
                *(__half2*)(outh + (size_t)r0 * CC + j0) = __floats2half2_rn(o0.x, o0.y);
            if (r1 < N_NODES)
                *(__half2*)(outh + (size_t)r1 * CC + j0) = __floats2half2_rn(o1.x, o1.y);
        } else {
            if (r0 < N_NODES) *(float2*)(outf + (size_t)r0 * CC + j0) = o0;
            if (r1 < N_NODES) *(float2*)(outf + (size_t)r1 * CC + j0) = o1;
        }
    }
}

extern "C" void kernel_launch(void* const* d_in, const int* in_sizes, int n_in,
                              void* d_out, int out_size) {
    const float* x   = (const float*)d_in[0];
    const int*   ei  = (const int*)d_in[1];
    const float* eps = (const float*)d_in[2];
    const float* W1  = (const float*)d_in[3];
    const float* b1  = (const float*)d_in[4];
    const float* g1  = (const float*)d_in[5];
    const float* be1 = (const float*)d_in[6];
    const float* W2  = (const float*)d_in[7];
    const float* b2  = (const float*)d_in[8];
    const float* g2  = (const float*)d_in[9];
    const float* be2 = (const float*)d_in[10];
    const float* bng = (const float*)d_in[11];
    const float* bnb = (const float*)d_in[12];
    float* out = (float*)d_out;

    __half *hb, *xh0, *xha, *xhb, *wfh;
    int *cnt, *off, *cur, *csr, *bsum;
    float *cv;
    cudaGetSymbolAddress((void**)&hb,   g_h);
    cudaGetSymbolAddress((void**)&xh0,  g_xh0);
    cudaGetSymbolAddress((void**)&xha,  g_xha);
    cudaGetSymbolAddress((void**)&xhb,  g_xhb);
    cudaGetSymbolAddress((void**)&cnt,  g_cnt);
    cudaGetSymbolAddress((void**)&off,  g_off);
    cudaGetSymbolAddress((void**)&cur,  g_cur);
    cudaGetSymbolAddress((void**)&csr,  g_csr);
    cudaGetSymbolAddress((void**)&bsum, g_bsum);
    cudaGetSymbolAddress((void**)&wfh,  g_wfh);
    cudaGetSymbolAddress((void**)&cv,   g_cv);

    cudaFuncSetAttribute(mlp_tc_kernel,
                         cudaFuncAttributeMaxDynamicSharedMemorySize, SB_TOT);

    const int eblk = (N_EDGES + 255) / 256;
    const int nblk = (N_NODES + 255) / 256;
    const int cblk = (N_NODES * CC / 4 + 255) / 256;    // 6250
    const int mlp_blocks = (N_NODES + 127) / 128;       // 782
    const int agg_blocks = (N_NODES * 32 + 255) / 256;  // 12500

    // CSR build (edge_index constant across layers) + conversions.
    cudaMemsetAsync(cnt, 0, N_NODES * sizeof(int));
    x2h_kernel<<<cblk, 256>>>(x, xh0);
    wconv_kernel<<<NL, 256>>>(W1, b1, g1, be1, W2, b2, g2, be2, bng, bnb, wfh, cv);
    hist_kernel<<<eblk, 256>>>(ei, cnt);
    scan_blocks_kernel<<<N_SCANB, SCAN_BLK>>>(cnt, off, bsum);
    scan_bsum_kernel<<<1, 128>>>(bsum);
    add_off_kernel<<<nblk, 256>>>(off, bsum, cur);
    fill_csr_kernel<<<eblk, 256>>>(ei, cur, csr);

    const __half* xin = xh0;
    __half* houts[NL] = {xha, xhb, nullptr};
    for (int l = 0; l < NL; l++) {
        agg_kernel<<<agg_blocks, 256>>>(xin, off, cnt, csr, eps, l, hb);
        int is_half = (l < NL - 1) ? 1 : 0;
        mlp_tc_kernel<<<mlp_blocks, 256, SB_TOT>>>(
            hb, out, houts[l], is_half,
            (const uint4*)(wfh + l * 2 * 4608), (const float4*)(cv + l * 256),
            (l < NL - 1) ? 1 : 0);
        xin = houts[l];
    }
}